// round 1
// baseline (speedup 1.0000x reference)
#include <cuda_runtime.h>
#include <stdint.h>

#define HH 768
#define WW 768
#define NPTS 200000
#define CIN 256
#define CB 64

// Scratch (allocation-free rule: __device__ globals)
static __device__ int   g_idx_map[HH * WW];
static __device__ int   g_coords[NPTS];
static __device__ float g_out1[(size_t)NPTS * CB];
static __device__ float g_out2[(size_t)NPTS * CB];

// Packed fp32x2 FMA: 2 FMAs per instruction (ptxas never emits this from C++)
__device__ __forceinline__ void ffma2(unsigned long long& acc,
                                      unsigned long long a,
                                      unsigned long long b) {
    asm("fma.rn.f32x2 %0, %1, %2, %0;" : "+l"(acc) : "l"(a), "l"(b));
}
__device__ __forceinline__ unsigned long long dup2(float a) {
    unsigned long long r;
    unsigned int u = __float_as_uint(a);
    asm("mov.b64 %0, {%1, %1};" : "=l"(r) : "r"(u));
    return r;
}
__device__ __forceinline__ float lo32(unsigned long long v) {
    return __uint_as_float((unsigned int)v);
}
__device__ __forceinline__ float hi32(unsigned long long v) {
    return __uint_as_float((unsigned int)(v >> 32));
}

// ---------------------------------------------------------------------------
// Kernel 0: idx_map = -1
__global__ void k_init_map() {
    int i = blockIdx.x * blockDim.x + threadIdx.x;
    if (i < HH * WW) g_idx_map[i] = -1;
}

// Kernel 1: coords (int32 or int64, detected from data) -> g_coords; scatter idx_map
__global__ void k_scatter(const void* __restrict__ coords_raw) {
    // If coords were int32, interpreting the first 8 bytes as int64 combines
    // coords[0] + (coords[1] << 32); coords are sorted unique so coords[1] >= 1
    // => value >= 2^32, far outside [0, HH*WW). Deterministic per-data branch.
    long long v0 = *(const long long*)coords_raw;
    bool is64 = (v0 >= 0 && v0 < (long long)(HH * WW));
    int i = blockIdx.x * blockDim.x + threadIdx.x;
    if (i < NPTS) {
        int c = is64 ? (int)((const long long*)coords_raw)[i]
                     : ((const int*)coords_raw)[i];
        g_coords[i] = c;
        g_idx_map[c] = i;
    }
}

// ---------------------------------------------------------------------------
// Kernel 2: out1 = relu((feats @ w1) * s1 + b1)      [N,256]@[256,64]
#define KT1 32
__global__ __launch_bounds__(128) void k_conv1(const float* __restrict__ feats,
                                               const float* __restrict__ w1,
                                               const float* __restrict__ s1,
                                               const float* __restrict__ b1) {
    __shared__ float sA[128][KT1 + 1];                 // 16.9 KB, pad -> conflict-free
    __shared__ __align__(16) float sW[KT1][CB];        // 8 KB
    const int t = threadIdx.x;
    const int base = blockIdx.x * 128;
    const int site = base + t;

    unsigned long long acc[CB / 2];
#pragma unroll
    for (int j = 0; j < CB / 2; j++) acc[j] = 0ULL;

    for (int kc = 0; kc < CIN; kc += KT1) {
        for (int l = t; l < 128 * KT1; l += 128) {
            int r = l / KT1, c = l % KT1;
            int sr = base + r; if (sr >= NPTS) sr = NPTS - 1;
            sA[r][c] = feats[(size_t)sr * CIN + kc + c];
        }
        for (int l = t; l < KT1 * CB; l += 128) {
            sW[l >> 6][l & 63] = w1[(size_t)(kc + (l >> 6)) * CB + (l & 63)];
        }
        __syncthreads();
#pragma unroll 4
        for (int kk = 0; kk < KT1; kk++) {
            unsigned long long aa = dup2(sA[t][kk]);
            const ulonglong2* wp = (const ulonglong2*)sW[kk];   // LDS.128, broadcast
#pragma unroll
            for (int j = 0; j < CB / 4; j++) {
                ulonglong2 w2v = wp[j];
                ffma2(acc[2 * j + 0], aa, w2v.x);
                ffma2(acc[2 * j + 1], aa, w2v.y);
            }
        }
        __syncthreads();
    }
    if (site < NPTS) {
#pragma unroll
        for (int j = 0; j < CB / 2; j++) {
            float2 sv = *(const float2*)&s1[2 * j];
            float2 bv = *(const float2*)&b1[2 * j];
            float lo = fmaxf(lo32(acc[j]) * sv.x + bv.x, 0.0f);
            float hi = fmaxf(hi32(acc[j]) * sv.y + bv.y, 0.0f);
            *(float2*)&g_out1[(size_t)site * CB + 2 * j] = make_float2(lo, hi);
        }
    }
}

// ---------------------------------------------------------------------------
// Kernel 3: out2 = relu(sparse_conv3x3(out1) * s2 + b2)   9 taps of [64x64]
__global__ __launch_bounds__(128) void k_conv2(const float* __restrict__ w2,
                                               const float* __restrict__ s2,
                                               const float* __restrict__ b2) {
    __shared__ float sG[128][CB + 1];                  // 33.3 KB gather tile
    __shared__ __align__(16) float sW[32][CB];         // 8 KB (half-K of one tap)
    __shared__ int sN[128];
    const int t = threadIdx.x;
    const int base = blockIdx.x * 128;
    const int site = base + t;
    const int cs = g_coords[min(site, NPTS - 1)];
    const int y = cs / WW, x = cs % WW;

    unsigned long long acc[CB / 2];
#pragma unroll
    for (int j = 0; j < CB / 2; j++) acc[j] = 0ULL;

    for (int k = 0; k < 9; k++) {
        const int dy = k / 3 - 1, dx = k % 3 - 1;
        int r = -1;
        int ny = y + dy, nx = x + dx;
        if (ny >= 0 && ny < HH && nx >= 0 && nx < WW) r = g_idx_map[ny * WW + nx];
        sN[t] = r;
        __syncthreads();
        // cooperative gather of 128 neighbor rows (coalesced 128B segments)
        for (int l = t; l < 128 * CB; l += 128) {
            int row = l >> 6, col = l & 63;
            int rr = sN[row];
            sG[row][col] = (rr >= 0) ? g_out1[(size_t)rr * CB + col] : 0.0f;
        }
        for (int h = 0; h < 2; h++) {
            __syncthreads();   // gather done (h=0) / previous compute done (h=1)
            for (int l = t; l < 32 * CB; l += 128) {
                sW[l >> 6][l & 63] =
                    w2[(size_t)k * CB * CB + (size_t)(h * 32 + (l >> 6)) * CB + (l & 63)];
            }
            __syncthreads();
#pragma unroll 4
            for (int kk = 0; kk < 32; kk++) {
                unsigned long long aa = dup2(sG[t][h * 32 + kk]);
                const ulonglong2* wp = (const ulonglong2*)sW[kk];
#pragma unroll
                for (int j = 0; j < CB / 4; j++) {
                    ulonglong2 w2v = wp[j];
                    ffma2(acc[2 * j + 0], aa, w2v.x);
                    ffma2(acc[2 * j + 1], aa, w2v.y);
                }
            }
        }
        __syncthreads();   // before next tap overwrites sN/sG
    }
    if (site < NPTS) {
#pragma unroll
        for (int j = 0; j < CB / 2; j++) {
            float2 sv = *(const float2*)&s2[2 * j];
            float2 bv = *(const float2*)&b2[2 * j];
            float lo = fmaxf(lo32(acc[j]) * sv.x + bv.x, 0.0f);
            float hi = fmaxf(hi32(acc[j]) * sv.y + bv.y, 0.0f);
            *(float2*)&g_out2[(size_t)site * CB + 2 * j] = make_float2(lo, hi);
        }
    }
}

// ---------------------------------------------------------------------------
// Kernel 4: out = relu((out2 @ w3) * s3 + b3 + feats)   [N,64]@[64,256]
// Warp-per-8-sites, lanes over column pairs: weight LDS coalesced & conflict-free.
#define KT3 8
__global__ __launch_bounds__(512) void k_conv3(const float* __restrict__ feats,
                                               const float* __restrict__ w3,
                                               const float* __restrict__ s3,
                                               const float* __restrict__ b3,
                                               float* __restrict__ out) {
    __shared__ float sO[128][CB];                      // 32 KB (broadcast reads only)
    __shared__ __align__(16) float sW[KT3][CIN];       // 8 KB
    const int t = threadIdx.x;
    const int warp = t >> 5, lane = t & 31;
    const int base = blockIdx.x * 128;

    for (int l = t; l < 128 * CB; l += 512) {
        int row = l >> 6, col = l & 63;
        int sr = base + row; if (sr >= NPTS) sr = NPTS - 1;
        sO[row][col] = g_out2[(size_t)sr * CB + col];
    }

    unsigned long long acc[8][4];
#pragma unroll
    for (int i = 0; i < 8; i++)
#pragma unroll
        for (int g = 0; g < 4; g++) acc[i][g] = 0ULL;

    for (int kc = 0; kc < CB; kc += KT3) {
        __syncthreads();   // sO ready (first iter) / sW consumers done (later)
        for (int l = t; l < KT3 * CIN; l += 512)
            sW[l >> 8][l & 255] = w3[(size_t)(kc + (l >> 8)) * CIN + (l & 255)];
        __syncthreads();
#pragma unroll
        for (int kk = 0; kk < KT3; kk++) {
            const unsigned long long* wr = (const unsigned long long*)sW[kk];
            unsigned long long w0 = wr[lane];
            unsigned long long w1v = wr[lane + 32];
            unsigned long long w2v = wr[lane + 64];
            unsigned long long w3v = wr[lane + 96];
#pragma unroll
            for (int i = 0; i < 8; i++) {
                unsigned long long aa = dup2(sO[warp * 8 + i][kc + kk]);
                ffma2(acc[i][0], aa, w0);
                ffma2(acc[i][1], aa, w1v);
                ffma2(acc[i][2], aa, w2v);
                ffma2(acc[i][3], aa, w3v);
            }
        }
    }
    // epilogue: scale/bias + residual + relu, coalesced float2 I/O
#pragma unroll
    for (int g = 0; g < 4; g++) {
        int col = 2 * lane + 64 * g;
        float2 sv = *(const float2*)&s3[col];
        float2 bv = *(const float2*)&b3[col];
#pragma unroll
        for (int i = 0; i < 8; i++) {
            int site = base + warp * 8 + i;
            if (site < NPTS) {
                float2 fv = *(const float2*)&feats[(size_t)site * CIN + col];
                float lo = fmaxf(lo32(acc[i][g]) * sv.x + bv.x + fv.x, 0.0f);
                float hi = fmaxf(hi32(acc[i][g]) * sv.y + bv.y + fv.y, 0.0f);
                *(float2*)&out[(size_t)site * CIN + col] = make_float2(lo, hi);
            }
        }
    }
}

// ---------------------------------------------------------------------------
extern "C" void kernel_launch(void* const* d_in, const int* in_sizes, int n_in,
                              void* d_out, int out_size) {
    const float* feats = (const float*)d_in[0];
    const void*  coords = d_in[1];
    const float* w1 = (const float*)d_in[2];
    const float* w2 = (const float*)d_in[3];
    const float* w3 = (const float*)d_in[4];
    const float* s1 = (const float*)d_in[5];
    const float* b1 = (const float*)d_in[6];
    const float* s2 = (const float*)d_in[7];
    const float* b2 = (const float*)d_in[8];
    const float* s3 = (const float*)d_in[9];
    const float* b3 = (const float*)d_in[10];
    float* out = (float*)d_out;

    k_init_map<<<(HH * WW + 255) / 256, 256>>>();
    k_scatter<<<(NPTS + 255) / 256, 256>>>(coords);
    k_conv1<<<(NPTS + 127) / 128, 128>>>(feats, w1, s1, b1);
    k_conv2<<<(NPTS + 127) / 128, 128>>>(w2, s2, b2);
    k_conv3<<<(NPTS + 127) / 128, 512>>>(feats, w3, s3, b3, out);
}

// round 3
// speedup vs baseline: 2.9051x; 2.9051x over previous
#include <cuda_runtime.h>
#include <cuda_bf16.h>
#include <stdint.h>

#define HH 768
#define WW 768
#define NPTS 200000
#define CIN 256
#define CB 64
#define NTILES ((NPTS + 127) / 128)

// ---------------------------------------------------------------------------
// Device scratch (allocation-free rule: __device__ globals)
static __device__ int g_idx_map[HH * WW];
static __device__ int g_coords[NPTS];
static __device__ __nv_bfloat16 g_o1h[(size_t)NPTS * CB];
static __device__ __nv_bfloat16 g_o1l[(size_t)NPTS * CB];
static __device__ __nv_bfloat16 g_o2h[(size_t)NPTS * CB];
static __device__ __nv_bfloat16 g_o2l[(size_t)NPTS * CB];
// Weight images in exact mma B-fragment order: entry[(kt*8+j)*32+lane] =
// {b0_hi, b1_hi, b0_lo, b1_lo} for a 64x64 (KxN) tile.
static __device__ uint4 g_w1p[4 * 1024];   // 4 K-chunks
static __device__ uint4 g_w2p[9 * 1024];   // 9 taps
static __device__ uint4 g_w3p[4 * 1024];   // 4 N-chunks

// ---------------------------------------------------------------------------
__device__ __forceinline__ uint32_t pack2(__nv_bfloat16 a, __nv_bfloat16 b) {
    __nv_bfloat162 p = __halves2bfloat162(a, b);   // .x = a (low 16 bits)
    return *reinterpret_cast<uint32_t*>(&p);
}
__device__ __forceinline__ void split_bf(float v, __nv_bfloat16& h, __nv_bfloat16& l) {
    h = __float2bfloat16_rn(v);
    l = __float2bfloat16_rn(v - __bfloat162float(h));
}
// m16n8k16 bf16 mma, accumulate in place
__device__ __forceinline__ void mma16816(float* c, const uint32_t* a,
                                         uint32_t b0, uint32_t b1) {
    asm volatile(
        "mma.sync.aligned.m16n8k16.row.col.f32.bf16.bf16.f32 "
        "{%0,%1,%2,%3}, {%4,%5,%6,%7}, {%8,%9}, {%0,%1,%2,%3};"
        : "+f"(c[0]), "+f"(c[1]), "+f"(c[2]), "+f"(c[3])
        : "r"(a[0]), "r"(a[1]), "r"(a[2]), "r"(a[3]), "r"(b0), "r"(b1));
}
// A-fragment from an smem bf16 plane with 144B row pitch
#define APITCH 144
__device__ __forceinline__ void load_afrag(const char* plane, int warpRow,
                                           int lane, int kbyte, uint32_t* a) {
    int g = lane >> 2, tid = lane & 3;
    const char* p = plane + (warpRow + g) * APITCH + kbyte + tid * 4;
    a[0] = *(const uint32_t*)p;
    a[1] = *(const uint32_t*)(p + 8 * APITCH);
    a[2] = *(const uint32_t*)(p + 16);
    a[3] = *(const uint32_t*)(p + 8 * APITCH + 16);
}

// ---------------------------------------------------------------------------
__global__ void k_init_map() {
    int i = blockIdx.x * blockDim.x + threadIdx.x;
    if (i < HH * WW) g_idx_map[i] = -1;
}

__global__ void k_scatter(const void* __restrict__ coords_raw) {
    long long v0 = *(const long long*)coords_raw;
    bool is64 = (v0 >= 0 && v0 < (long long)(HH * WW));
    int i = blockIdx.x * blockDim.x + threadIdx.x;
    if (i < NPTS) {
        int c = is64 ? (int)((const long long*)coords_raw)[i]
                     : ((const int*)coords_raw)[i];
        g_coords[i] = c;
        g_idx_map[c] = i;
    }
}

// Pack all weights into B-fragment-ordered hi/lo images (17 tiles x 1024 entries)
__global__ void k_prep(const float* __restrict__ w1, const float* __restrict__ w2,
                       const float* __restrict__ w3) {
    int i = blockIdx.x * blockDim.x + threadIdx.x;
    if (i >= 17 * 1024) return;
    int tile = i >> 10, e = i & 1023;
    int kt = e >> 8, j = (e >> 5) & 7, lane = e & 31;
    int g = lane >> 2, tid = lane & 3;
    int n = j * 8 + g;
    int k0 = kt * 16 + tid * 2;
    float v00, v01, v10, v11;   // B[k0][n], B[k0+1][n], B[k0+8][n], B[k0+9][n]
    if (tile < 4) {
        int kb = tile * 64;
        v00 = w1[(size_t)(kb + k0) * 64 + n];
        v01 = w1[(size_t)(kb + k0 + 1) * 64 + n];
        v10 = w1[(size_t)(kb + k0 + 8) * 64 + n];
        v11 = w1[(size_t)(kb + k0 + 9) * 64 + n];
    } else if (tile < 13) {
        const float* wp = w2 + (size_t)(tile - 4) * 4096;
        v00 = wp[k0 * 64 + n];
        v01 = wp[(k0 + 1) * 64 + n];
        v10 = wp[(k0 + 8) * 64 + n];
        v11 = wp[(k0 + 9) * 64 + n];
    } else {
        int nb = (tile - 13) * 64;
        v00 = w3[(size_t)k0 * 256 + nb + n];
        v01 = w3[(size_t)(k0 + 1) * 256 + nb + n];
        v10 = w3[(size_t)(k0 + 8) * 256 + nb + n];
        v11 = w3[(size_t)(k0 + 9) * 256 + nb + n];
    }
    __nv_bfloat16 h00, l00, h01, l01, h10, l10, h11, l11;
    split_bf(v00, h00, l00); split_bf(v01, h01, l01);
    split_bf(v10, h10, l10); split_bf(v11, h11, l11);
    uint4 o;
    o.x = pack2(h00, h01);   // b0 hi
    o.y = pack2(h10, h11);   // b1 hi
    o.z = pack2(l00, l01);   // b0 lo
    o.w = pack2(l10, l11);   // b1 lo
    uint4* dst = (tile < 4) ? &g_w1p[tile * 1024]
               : (tile < 13) ? &g_w2p[(tile - 4) * 1024]
                             : &g_w3p[(tile - 13) * 1024];
    dst[e] = o;
}

// ---------------------------------------------------------------------------
// conv1: out1 = relu((feats @ w1) * s1 + b1) -> bf16 hi/lo planes
__global__ __launch_bounds__(256) void k_conv1(const float* __restrict__ feats,
                                               const float* __restrict__ s1,
                                               const float* __restrict__ b1) {
    __shared__ __align__(16) char sAh[128 * APITCH];
    __shared__ __align__(16) char sAl[128 * APITCH];
    const int t = threadIdx.x, lane = t & 31, warp = t >> 5;
    const int warpRow = warp * 16;
    const int base = blockIdx.x * 128;

    float acc[8][4];
#pragma unroll
    for (int j = 0; j < 8; j++)
#pragma unroll
        for (int q = 0; q < 4; q++) acc[j][q] = 0.f;

    for (int c = 0; c < 4; c++) {
        __syncthreads();   // planes free
#pragma unroll
        for (int p = 0; p < 8; p++) {
            int idx = t + p * 256;
            int row = idx >> 4, q = idx & 15;
            int sr = base + row; if (sr >= NPTS) sr = NPTS - 1;
            float4 v = *(const float4*)&feats[(size_t)sr * CIN + c * 64 + q * 4];
            __nv_bfloat16 h0, l0, h1, l1, h2, l2, h3, l3;
            split_bf(v.x, h0, l0); split_bf(v.y, h1, l1);
            split_bf(v.z, h2, l2); split_bf(v.w, h3, l3);
            uint2 H = make_uint2(pack2(h0, h1), pack2(h2, h3));
            uint2 L = make_uint2(pack2(l0, l1), pack2(l2, l3));
            *(uint2*)(sAh + row * APITCH + q * 8) = H;
            *(uint2*)(sAl + row * APITCH + q * 8) = L;
        }
        __syncthreads();
        const uint4* wimg = g_w1p + c * 1024;
#pragma unroll
        for (int kt = 0; kt < 4; kt++) {
            uint32_t ah[4], al[4];
            load_afrag(sAh, warpRow, lane, kt * 32, ah);
            load_afrag(sAl, warpRow, lane, kt * 32, al);
#pragma unroll
            for (int j = 0; j < 8; j++) {
                uint4 b = __ldg(&wimg[(kt * 8 + j) * 32 + lane]);
                mma16816(acc[j], ah, b.x, b.y);
                mma16816(acc[j], ah, b.z, b.w);
                mma16816(acc[j], al, b.x, b.y);
            }
        }
    }
    // epilogue: bn + relu + split-store
    const int g = lane >> 2, tid = lane & 3;
    const int r0 = base + warpRow + g, r1 = r0 + 8;
#pragma unroll
    for (int j = 0; j < 8; j++) {
        int col = j * 8 + tid * 2;
        float2 sv = *(const float2*)&s1[col];
        float2 bv = *(const float2*)&b1[col];
        if (r0 < NPTS) {
            float v0 = fmaxf(acc[j][0] * sv.x + bv.x, 0.f);
            float v1 = fmaxf(acc[j][1] * sv.y + bv.y, 0.f);
            __nv_bfloat16 h0, l0, h1, l1;
            split_bf(v0, h0, l0); split_bf(v1, h1, l1);
            *(uint32_t*)&g_o1h[(size_t)r0 * CB + col] = pack2(h0, h1);
            *(uint32_t*)&g_o1l[(size_t)r0 * CB + col] = pack2(l0, l1);
        }
        if (r1 < NPTS) {
            float v0 = fmaxf(acc[j][2] * sv.x + bv.x, 0.f);
            float v1 = fmaxf(acc[j][3] * sv.y + bv.y, 0.f);
            __nv_bfloat16 h0, l0, h1, l1;
            split_bf(v0, h0, l0); split_bf(v1, h1, l1);
            *(uint32_t*)&g_o1h[(size_t)r1 * CB + col] = pack2(h0, h1);
            *(uint32_t*)&g_o1l[(size_t)r1 * CB + col] = pack2(l0, l1);
        }
    }
}

// ---------------------------------------------------------------------------
// conv2: out2 = relu(sparse3x3(out1) * s2 + b2); 9 taps accumulate in registers
__global__ __launch_bounds__(256) void k_conv2(const float* __restrict__ s2,
                                               const float* __restrict__ b2) {
    __shared__ __align__(16) char sAh[128 * APITCH];
    __shared__ __align__(16) char sAl[128 * APITCH];
    __shared__ int sN[128];
    const int t = threadIdx.x, lane = t & 31, warp = t >> 5;
    const int warpRow = warp * 16;
    const int base = blockIdx.x * 128;

    int y = 0, x = 0;
    if (t < 128) {
        int cs = g_coords[min(base + t, NPTS - 1)];
        y = cs / WW; x = cs % WW;
    }

    float acc[8][4];
#pragma unroll
    for (int j = 0; j < 8; j++)
#pragma unroll
        for (int q = 0; q < 4; q++) acc[j][q] = 0.f;

    for (int tap = 0; tap < 9; tap++) {
        if (t < 128) {
            int dy = tap / 3 - 1, dx = tap % 3 - 1;
            int ny = y + dy, nx = x + dx;
            int r = -1;
            if (ny >= 0 && ny < HH && nx >= 0 && nx < WW) r = g_idx_map[ny * WW + nx];
            sN[t] = r;
        }
        __syncthreads();   // prev mma done + sN visible
        // gather neighbor rows into planes: 128 rows x 2 planes x 8 uint4
#pragma unroll
        for (int p = 0; p < 8; p++) {
            int idx = t + p * 256;
            int row = idx >> 4, q = idx & 15;
            int plane = q >> 3, c16 = q & 7;
            int rr = sN[row];
            uint4 v = make_uint4(0, 0, 0, 0);
            if (rr >= 0) {
                const __nv_bfloat16* src = plane ? g_o1l : g_o1h;
                v = *(const uint4*)(src + (size_t)rr * CB + c16 * 8);
            }
            char* dst = plane ? sAl : sAh;
            *(uint4*)(dst + row * APITCH + c16 * 16) = v;
        }
        __syncthreads();
        const uint4* wimg = g_w2p + tap * 1024;
#pragma unroll
        for (int kt = 0; kt < 4; kt++) {
            uint32_t ah[4], al[4];
            load_afrag(sAh, warpRow, lane, kt * 32, ah);
            load_afrag(sAl, warpRow, lane, kt * 32, al);
#pragma unroll
            for (int j = 0; j < 8; j++) {
                uint4 b = __ldg(&wimg[(kt * 8 + j) * 32 + lane]);
                mma16816(acc[j], ah, b.x, b.y);
                mma16816(acc[j], ah, b.z, b.w);
                mma16816(acc[j], al, b.x, b.y);
            }
        }
    }
    const int g = lane >> 2, tid = lane & 3;
    const int r0 = base + warpRow + g, r1 = r0 + 8;
#pragma unroll
    for (int j = 0; j < 8; j++) {
        int col = j * 8 + tid * 2;
        float2 sv = *(const float2*)&s2[col];
        float2 bv = *(const float2*)&b2[col];
        if (r0 < NPTS) {
            float v0 = fmaxf(acc[j][0] * sv.x + bv.x, 0.f);
            float v1 = fmaxf(acc[j][1] * sv.y + bv.y, 0.f);
            __nv_bfloat16 h0, l0, h1, l1;
            split_bf(v0, h0, l0); split_bf(v1, h1, l1);
            *(uint32_t*)&g_o2h[(size_t)r0 * CB + col] = pack2(h0, h1);
            *(uint32_t*)&g_o2l[(size_t)r0 * CB + col] = pack2(l0, l1);
        }
        if (r1 < NPTS) {
            float v0 = fmaxf(acc[j][2] * sv.x + bv.x, 0.f);
            float v1 = fmaxf(acc[j][3] * sv.y + bv.y, 0.f);
            __nv_bfloat16 h0, l0, h1, l1;
            split_bf(v0, h0, l0); split_bf(v1, h1, l1);
            *(uint32_t*)&g_o2h[(size_t)r1 * CB + col] = pack2(h0, h1);
            *(uint32_t*)&g_o2l[(size_t)r1 * CB + col] = pack2(l0, l1);
        }
    }
}

// ---------------------------------------------------------------------------
// conv3: out = relu((out2 @ w3) * s3 + b3 + feats); N=256 in 4 chunks
__global__ __launch_bounds__(256) void k_conv3(const float* __restrict__ feats,
                                               const float* __restrict__ s3,
                                               const float* __restrict__ b3,
                                               float* __restrict__ out) {
    __shared__ __align__(16) char sAh[128 * APITCH];
    __shared__ __align__(16) char sAl[128 * APITCH];
    const int t = threadIdx.x, lane = t & 31, warp = t >> 5;
    const int warpRow = warp * 16;
    const int base = blockIdx.x * 128;

    // stage A once (reused by all 4 N-chunks)
#pragma unroll
    for (int p = 0; p < 8; p++) {
        int idx = t + p * 256;
        int row = idx >> 4, q = idx & 15;
        int plane = q >> 3, c16 = q & 7;
        int sr = base + row; if (sr >= NPTS) sr = NPTS - 1;
        const __nv_bfloat16* src = plane ? g_o2l : g_o2h;
        uint4 v = *(const uint4*)(src + (size_t)sr * CB + c16 * 8);
        char* dst = plane ? sAl : sAh;
        *(uint4*)(dst + row * APITCH + c16 * 16) = v;
    }
    __syncthreads();
    const int g = lane >> 2, tid = lane & 3;
    const int r0 = base + warpRow + g, r1 = r0 + 8;

    for (int nc = 0; nc < 4; nc++) {
        float acc[8][4];
#pragma unroll
        for (int j = 0; j < 8; j++)
#pragma unroll
            for (int q = 0; q < 4; q++) acc[j][q] = 0.f;
        const uint4* wimg = g_w3p + nc * 1024;
#pragma unroll
        for (int kt = 0; kt < 4; kt++) {
            uint32_t ah[4], al[4];
            load_afrag(sAh, warpRow, lane, kt * 32, ah);
            load_afrag(sAl, warpRow, lane, kt * 32, al);
#pragma unroll
            for (int j = 0; j < 8; j++) {
                uint4 b = __ldg(&wimg[(kt * 8 + j) * 32 + lane]);
                mma16816(acc[j], ah, b.x, b.y);
                mma16816(acc[j], ah, b.z, b.w);
                mma16816(acc[j], al, b.x, b.y);
            }
        }
        // epilogue with residual
#pragma unroll
        for (int j = 0; j < 8; j++) {
            int col = nc * 64 + j * 8 + tid * 2;
            float2 sv = *(const float2*)&s3[col];
            float2 bv = *(const float2*)&b3[col];
            if (r0 < NPTS) {
                float2 fv = *(const float2*)&feats[(size_t)r0 * CIN + col];
                float2 o;
                o.x = fmaxf(acc[j][0] * sv.x + bv.x + fv.x, 0.f);
                o.y = fmaxf(acc[j][1] * sv.y + bv.y + fv.y, 0.f);
                *(float2*)&out[(size_t)r0 * CIN + col] = o;
            }
            if (r1 < NPTS) {
                float2 fv = *(const float2*)&feats[(size_t)r1 * CIN + col];
                float2 o;
                o.x = fmaxf(acc[j][2] * sv.x + bv.x + fv.x, 0.f);
                o.y = fmaxf(acc[j][3] * sv.y + bv.y + fv.y, 0.f);
                *(float2*)&out[(size_t)r1 * CIN + col] = o;
            }
        }
    }
}

// ---------------------------------------------------------------------------
extern "C" void kernel_launch(void* const* d_in, const int* in_sizes, int n_in,
                              void* d_out, int out_size) {
    const float* feats = (const float*)d_in[0];
    const void*  coords = d_in[1];
    const float* w1 = (const float*)d_in[2];
    const float* w2 = (const float*)d_in[3];
    const float* w3 = (const float*)d_in[4];
    const float* s1 = (const float*)d_in[5];
    const float* b1 = (const float*)d_in[6];
    const float* s2 = (const float*)d_in[7];
    const float* b2 = (const float*)d_in[8];
    const float* s3 = (const float*)d_in[9];
    const float* b3 = (const float*)d_in[10];
    float* out = (float*)d_out;

    k_init_map<<<(HH * WW + 255) / 256, 256>>>();
    k_scatter<<<(NPTS + 255) / 256, 256>>>(coords);
    k_prep<<<(17 * 1024 + 255) / 256, 256>>>(w1, w2, w3);
    k_conv1<<<NTILES, 256>>>(feats, s1, b1);
    k_conv2<<<NTILES, 256>>>(s2, b2);
    k_conv3<<<NTILES, 256>>>(feats, s3, b3, out);
}

// round 5
// speedup vs baseline: 3.7903x; 1.3047x over previous
#include <cuda_runtime.h>
#include <cuda_bf16.h>
#include <stdint.h>

#define HH 768
#define WW 768
#define NPTS 200000
#define CIN 256
#define CB 64
#define NTILES ((NPTS + 127) / 128)

// ---------------------------------------------------------------------------
static __device__ int g_idx_map[HH * WW];
static __device__ int g_coords[NPTS];
static __device__ __nv_bfloat16 g_o1h[(size_t)NPTS * CB];
static __device__ __nv_bfloat16 g_o1l[(size_t)NPTS * CB];
static __device__ __nv_bfloat16 g_o2h[(size_t)NPTS * CB];
static __device__ __nv_bfloat16 g_o2l[(size_t)NPTS * CB];
// Weight images in mma B-fragment order: entry[(kt*8+j)*32+lane] =
// {b0_hi, b1_hi, b0_lo, b1_lo} for a 64x64 (KxN) tile.
static __device__ uint4 g_w1p[4 * 1024];
static __device__ uint4 g_w2p[9 * 1024];
static __device__ uint4 g_w3p[4 * 1024];

// ---------------------------------------------------------------------------
__device__ __forceinline__ uint32_t pack2(__nv_bfloat16 a, __nv_bfloat16 b) {
    __nv_bfloat162 p = __halves2bfloat162(a, b);
    return *reinterpret_cast<uint32_t*>(&p);
}
__device__ __forceinline__ void split_bf(float v, __nv_bfloat16& h, __nv_bfloat16& l) {
    h = __float2bfloat16_rn(v);
    l = __float2bfloat16_rn(v - __bfloat162float(h));
}
__device__ __forceinline__ void mma16816(float* c, const uint32_t* a,
                                         uint32_t b0, uint32_t b1) {
    asm volatile(
        "mma.sync.aligned.m16n8k16.row.col.f32.bf16.bf16.f32 "
        "{%0,%1,%2,%3}, {%4,%5,%6,%7}, {%8,%9}, {%0,%1,%2,%3};"
        : "+f"(c[0]), "+f"(c[1]), "+f"(c[2]), "+f"(c[3])
        : "r"(a[0]), "r"(a[1]), "r"(a[2]), "r"(a[3]), "r"(b0), "r"(b1));
}
// Half-K plane: 128 rows x 32 bf16 cols, pitch 80B
#define HPITCH 80
__device__ __forceinline__ void load_afrag(const char* plane, int warpRow,
                                           int lane, int kbyte, uint32_t* a) {
    int g = lane >> 2, tid = lane & 3;
    const char* p = plane + (warpRow + g) * HPITCH + kbyte + tid * 4;
    a[0] = *(const uint32_t*)p;
    a[1] = *(const uint32_t*)(p + 8 * HPITCH);
    a[2] = *(const uint32_t*)(p + 16);
    a[3] = *(const uint32_t*)(p + 8 * HPITCH + 16);
}
// Full-K plane (conv3): 128 rows x 64 bf16 cols, pitch 144B
#define FPITCH 144
__device__ __forceinline__ void load_afragF(const char* plane, int warpRow,
                                            int lane, int kbyte, uint32_t* a) {
    int g = lane >> 2, tid = lane & 3;
    const char* p = plane + (warpRow + g) * FPITCH + kbyte + tid * 4;
    a[0] = *(const uint32_t*)p;
    a[1] = *(const uint32_t*)(p + 8 * FPITCH);
    a[2] = *(const uint32_t*)(p + 16);
    a[3] = *(const uint32_t*)(p + 8 * FPITCH + 16);
}

// ---------------------------------------------------------------------------
__global__ void k_init_map() {
    int i = blockIdx.x * blockDim.x + threadIdx.x;
    if (i < HH * WW) g_idx_map[i] = -1;
}

__global__ void k_scatter(const void* __restrict__ coords_raw) {
    long long v0 = *(const long long*)coords_raw;
    bool is64 = (v0 >= 0 && v0 < (long long)(HH * WW));
    int i = blockIdx.x * blockDim.x + threadIdx.x;
    if (i < NPTS) {
        int c = is64 ? (int)((const long long*)coords_raw)[i]
                     : ((const int*)coords_raw)[i];
        g_coords[i] = c;
        g_idx_map[c] = i;
    }
}

__global__ void k_prep(const float* __restrict__ w1, const float* __restrict__ w2,
                       const float* __restrict__ w3) {
    int i = blockIdx.x * blockDim.x + threadIdx.x;
    if (i >= 17 * 1024) return;
    int tile = i >> 10, e = i & 1023;
    int kt = e >> 8, j = (e >> 5) & 7, lane = e & 31;
    int g = lane >> 2, tid = lane & 3;
    int n = j * 8 + g;
    int k0 = kt * 16 + tid * 2;
    float v00, v01, v10, v11;
    if (tile < 4) {
        int kb = tile * 64;
        v00 = w1[(size_t)(kb + k0) * 64 + n];
        v01 = w1[(size_t)(kb + k0 + 1) * 64 + n];
        v10 = w1[(size_t)(kb + k0 + 8) * 64 + n];
        v11 = w1[(size_t)(kb + k0 + 9) * 64 + n];
    } else if (tile < 13) {
        const float* wp = w2 + (size_t)(tile - 4) * 4096;
        v00 = wp[k0 * 64 + n];
        v01 = wp[(k0 + 1) * 64 + n];
        v10 = wp[(k0 + 8) * 64 + n];
        v11 = wp[(k0 + 9) * 64 + n];
    } else {
        int nb = (tile - 13) * 64;
        v00 = w3[(size_t)k0 * 256 + nb + n];
        v01 = w3[(size_t)(k0 + 1) * 256 + nb + n];
        v10 = w3[(size_t)(k0 + 8) * 256 + nb + n];
        v11 = w3[(size_t)(k0 + 9) * 256 + nb + n];
    }
    __nv_bfloat16 h00, l00, h01, l01, h10, l10, h11, l11;
    split_bf(v00, h00, l00); split_bf(v01, h01, l01);
    split_bf(v10, h10, l10); split_bf(v11, h11, l11);
    uint4 o;
    o.x = pack2(h00, h01);
    o.y = pack2(h10, h11);
    o.z = pack2(l00, l01);
    o.w = pack2(l10, l11);
    uint4* dst = (tile < 4) ? &g_w1p[tile * 1024]
               : (tile < 13) ? &g_w2p[(tile - 4) * 1024]
                             : &g_w3p[(tile - 13) * 1024];
    dst[e] = o;
}

// ---------------------------------------------------------------------------
// conv1: out1 = relu((feats @ w1) * s1 + b1); pipelined 8 half-K stages
__global__ __launch_bounds__(256, 2) void k_conv1(const float* __restrict__ feats,
                                                  const float* __restrict__ s1,
                                                  const float* __restrict__ b1) {
    __shared__ __align__(16) char sA[2][2][128 * HPITCH];   // [buf][hi/lo] 40KB
    const int t = threadIdx.x, lane = t & 31, warp = t >> 5;
    const int warpRow = warp * 16;
    const int base = blockIdx.x * 128;

    float acc[8][4];
#pragma unroll
    for (int j = 0; j < 8; j++)
#pragma unroll
        for (int q = 0; q < 4; q++) acc[j][q] = 0.f;

    // stage slice: 128 rows x 8 float4/row = 1024 float4; thread t, part p:
    // row = (t>>3) + p*32, q = t&7
    const int srow0 = t >> 3, sq = t & 7;
    float4 pre[4];
#pragma unroll
    for (int p = 0; p < 4; p++) {
        int row = srow0 + p * 32;
        int sr = base + row; if (sr >= NPTS) sr = NPTS - 1;
        pre[p] = *(const float4*)&feats[(size_t)sr * CIN + sq * 4];   // stage 0
    }

    for (int s = 0; s < 8; s++) {
        const int buf = s & 1;
        // store prefetched stage s
#pragma unroll
        for (int p = 0; p < 4; p++) {
            int row = srow0 + p * 32;
            float4 v = pre[p];
            __nv_bfloat16 h0, l0, h1, l1, h2, l2, h3, l3;
            split_bf(v.x, h0, l0); split_bf(v.y, h1, l1);
            split_bf(v.z, h2, l2); split_bf(v.w, h3, l3);
            *(uint2*)(sA[buf][0] + row * HPITCH + sq * 8) =
                make_uint2(pack2(h0, h1), pack2(h2, h3));
            *(uint2*)(sA[buf][1] + row * HPITCH + sq * 8) =
                make_uint2(pack2(l0, l1), pack2(l2, l3));
        }
        // issue loads for stage s+1 (overlap with this stage's MMAs)
        if (s < 7) {
            int c = (s + 1) >> 1, h = (s + 1) & 1;
#pragma unroll
            for (int p = 0; p < 4; p++) {
                int row = srow0 + p * 32;
                int sr = base + row; if (sr >= NPTS) sr = NPTS - 1;
                pre[p] = *(const float4*)&feats[(size_t)sr * CIN + c * 64 + h * 32 + sq * 4];
            }
        }
        __syncthreads();
        const int c = s >> 1, h = s & 1;
        const uint4* wimg = g_w1p + c * 1024;
#pragma unroll
        for (int ktl = 0; ktl < 2; ktl++) {
            int ktg = h * 2 + ktl;
            uint32_t ah[4], al[4];
            load_afrag(sA[buf][0], warpRow, lane, ktl * 32, ah);
            load_afrag(sA[buf][1], warpRow, lane, ktl * 32, al);
#pragma unroll
            for (int j = 0; j < 8; j++) {
                uint4 b = __ldg(&wimg[(ktg * 8 + j) * 32 + lane]);
                mma16816(acc[j], ah, b.x, b.y);
                mma16816(acc[j], ah, b.z, b.w);
                mma16816(acc[j], al, b.x, b.y);
            }
        }
    }
    // epilogue
    const int g = lane >> 2, tid = lane & 3;
    const int r0 = base + warpRow + g, r1 = r0 + 8;
#pragma unroll
    for (int j = 0; j < 8; j++) {
        int col = j * 8 + tid * 2;
        float2 sv = *(const float2*)&s1[col];
        float2 bv = *(const float2*)&b1[col];
        if (r0 < NPTS) {
            float v0 = fmaxf(acc[j][0] * sv.x + bv.x, 0.f);
            float v1 = fmaxf(acc[j][1] * sv.y + bv.y, 0.f);
            __nv_bfloat16 h0, l0, h1, l1;
            split_bf(v0, h0, l0); split_bf(v1, h1, l1);
            *(uint32_t*)&g_o1h[(size_t)r0 * CB + col] = pack2(h0, h1);
            *(uint32_t*)&g_o1l[(size_t)r0 * CB + col] = pack2(l0, l1);
        }
        if (r1 < NPTS) {
            float v0 = fmaxf(acc[j][2] * sv.x + bv.x, 0.f);
            float v1 = fmaxf(acc[j][3] * sv.y + bv.y, 0.f);
            __nv_bfloat16 h0, l0, h1, l1;
            split_bf(v0, h0, l0); split_bf(v1, h1, l1);
            *(uint32_t*)&g_o1h[(size_t)r1 * CB + col] = pack2(h0, h1);
            *(uint32_t*)&g_o1l[(size_t)r1 * CB + col] = pack2(l0, l1);
        }
    }
}

// ---------------------------------------------------------------------------
// conv2: out2 = relu(sparse3x3(out1) * s2 + b2); 18 pipelined stages (9 taps x 2)
__global__ __launch_bounds__(256, 2) void k_conv2(const float* __restrict__ s2,
                                                  const float* __restrict__ b2) {
    __shared__ __align__(16) char sA[2][2][128 * HPITCH];   // 40KB
    __shared__ int sN[9][128];                               // 4.6KB
    const int t = threadIdx.x, lane = t & 31, warp = t >> 5;
    const int warpRow = warp * 16;
    const int base = blockIdx.x * 128;

    // precompute all 9 neighbor indices
    if (t < 128) {
        int cs = g_coords[min(base + t, NPTS - 1)];
        int y = cs / WW, x = cs % WW;
#pragma unroll
        for (int tap = 0; tap < 9; tap++) {
            int ny = y + tap / 3 - 1, nx = x + tap % 3 - 1;
            int r = -1;
            if (ny >= 0 && ny < HH && nx >= 0 && nx < WW) r = g_idx_map[ny * WW + nx];
            sN[tap][t] = r;
        }
    }
    __syncthreads();

    float acc[8][4];
#pragma unroll
    for (int j = 0; j < 8; j++)
#pragma unroll
        for (int q = 0; q < 4; q++) acc[j][q] = 0.f;

    // stage slice: 128 rows x 2 planes x 4 uint4/row-plane = 1024 uint4;
    // thread t, part p: row = (t>>3)+p*32, plane = (t>>2)&1, q = t&3
    const int grow = t >> 3, gplane = (t >> 2) & 1, gq = t & 3;
    uint4 pre[4];
    {
        const __nv_bfloat16* src = gplane ? g_o1l : g_o1h;
#pragma unroll
        for (int p = 0; p < 4; p++) {
            int rr = sN[0][grow + p * 32];
            pre[p] = (rr >= 0) ? *(const uint4*)(src + (size_t)rr * CB + gq * 8)
                               : make_uint4(0, 0, 0, 0);
        }
    }

    for (int s = 0; s < 18; s++) {
        const int buf = s & 1;
#pragma unroll
        for (int p = 0; p < 4; p++) {
            char* dst = sA[buf][gplane];
            *(uint4*)(dst + (grow + p * 32) * HPITCH + gq * 16) = pre[p];
        }
        if (s < 17) {
            int tap = (s + 1) >> 1, h = (s + 1) & 1;
            const __nv_bfloat16* src = gplane ? g_o1l : g_o1h;
#pragma unroll
            for (int p = 0; p < 4; p++) {
                int rr = sN[tap][grow + p * 32];
                pre[p] = (rr >= 0)
                    ? *(const uint4*)(src + (size_t)rr * CB + h * 32 + gq * 8)
                    : make_uint4(0, 0, 0, 0);
            }
        }
        __syncthreads();
        const int tap = s >> 1, h = s & 1;
        const uint4* wimg = g_w2p + tap * 1024;
#pragma unroll
        for (int ktl = 0; ktl < 2; ktl++) {
            int ktg = h * 2 + ktl;
            uint32_t ah[4], al[4];
            load_afrag(sA[buf][0], warpRow, lane, ktl * 32, ah);
            load_afrag(sA[buf][1], warpRow, lane, ktl * 32, al);
#pragma unroll
            for (int j = 0; j < 8; j++) {
                uint4 b = __ldg(&wimg[(ktg * 8 + j) * 32 + lane]);
                mma16816(acc[j], ah, b.x, b.y);
                mma16816(acc[j], ah, b.z, b.w);
                mma16816(acc[j], al, b.x, b.y);
            }
        }
    }
    const int g = lane >> 2, tid = lane & 3;
    const int r0 = base + warpRow + g, r1 = r0 + 8;
#pragma unroll
    for (int j = 0; j < 8; j++) {
        int col = j * 8 + tid * 2;
        float2 sv = *(const float2*)&s2[col];
        float2 bv = *(const float2*)&b2[col];
        if (r0 < NPTS) {
            float v0 = fmaxf(acc[j][0] * sv.x + bv.x, 0.f);
            float v1 = fmaxf(acc[j][1] * sv.y + bv.y, 0.f);
            __nv_bfloat16 h0, l0, h1, l1;
            split_bf(v0, h0, l0); split_bf(v1, h1, l1);
            *(uint32_t*)&g_o2h[(size_t)r0 * CB + col] = pack2(h0, h1);
            *(uint32_t*)&g_o2l[(size_t)r0 * CB + col] = pack2(l0, l1);
        }
        if (r1 < NPTS) {
            float v0 = fmaxf(acc[j][2] * sv.x + bv.x, 0.f);
            float v1 = fmaxf(acc[j][3] * sv.y + bv.y, 0.f);
            __nv_bfloat16 h0, l0, h1, l1;
            split_bf(v0, h0, l0); split_bf(v1, h1, l1);
            *(uint32_t*)&g_o2h[(size_t)r1 * CB + col] = pack2(h0, h1);
            *(uint32_t*)&g_o2l[(size_t)r1 * CB + col] = pack2(l0, l1);
        }
    }
}

// ---------------------------------------------------------------------------
// conv3: out = relu((out2 @ w3) * s3 + b3 + feats); A staged once, 4 N-chunks
__global__ __launch_bounds__(256, 2) void k_conv3(const float* __restrict__ feats,
                                                  const float* __restrict__ s3,
                                                  const float* __restrict__ b3,
                                                  float* __restrict__ out) {
    __shared__ __align__(16) char sAh[128 * FPITCH];
    __shared__ __align__(16) char sAl[128 * FPITCH];
    const int t = threadIdx.x, lane = t & 31, warp = t >> 5;
    const int warpRow = warp * 16;
    const int base = blockIdx.x * 128;

#pragma unroll
    for (int p = 0; p < 8; p++) {
        int idx = t + p * 256;
        int row = idx >> 4, q = idx & 15;
        int plane = q >> 3, c16 = q & 7;
        int sr = base + row; if (sr >= NPTS) sr = NPTS - 1;
        const __nv_bfloat16* src = plane ? g_o2l : g_o2h;
        uint4 v = *(const uint4*)(src + (size_t)sr * CB + c16 * 8);
        char* dst = plane ? sAl : sAh;
        *(uint4*)(dst + row * FPITCH + c16 * 16) = v;
    }
    __syncthreads();
    const int g = lane >> 2, tid = lane & 3;
    const int r0 = base + warpRow + g, r1 = r0 + 8;

    uint32_t ah[4][4], al[4][4];
#pragma unroll
    for (int kt = 0; kt < 4; kt++) {
        load_afragF(sAh, warpRow, lane, kt * 32, ah[kt]);
        load_afragF(sAl, warpRow, lane, kt * 32, al[kt]);
    }

    for (int nc = 0; nc < 4; nc++) {
        float acc[8][4];
#pragma unroll
        for (int j = 0; j < 8; j++)
#pragma unroll
            for (int q = 0; q < 4; q++) acc[j][q] = 0.f;
        const uint4* wimg = g_w3p + nc * 1024;
#pragma unroll
        for (int kt = 0; kt < 4; kt++) {
#pragma unroll
            for (int j = 0; j < 8; j++) {
                uint4 b = __ldg(&wimg[(kt * 8 + j) * 32 + lane]);
                mma16816(acc[j], ah[kt], b.x, b.y);
                mma16816(acc[j], ah[kt], b.z, b.w);
                mma16816(acc[j], al[kt], b.x, b.y);
            }
        }
#pragma unroll
        for (int j = 0; j < 8; j++) {
            int col = nc * 64 + j * 8 + tid * 2;
            float2 sv = *(const float2*)&s3[col];
            float2 bv = *(const float2*)&b3[col];
            if (r0 < NPTS) {
                float2 fv = *(const float2*)&feats[(size_t)r0 * CIN + col];
                float2 o;
                o.x = fmaxf(acc[j][0] * sv.x + bv.x + fv.x, 0.f);
                o.y = fmaxf(acc[j][1] * sv.y + bv.y + fv.y, 0.f);
                *(float2*)&out[(size_t)r0 * CIN + col] = o;
            }
            if (r1 < NPTS) {
                float2 fv = *(const float2*)&feats[(size_t)r1 * CIN + col];
                float2 o;
                o.x = fmaxf(acc[j][2] * sv.x + bv.x + fv.x, 0.f);
                o.y = fmaxf(acc[j][3] * sv.y + bv.y + fv.y, 0.f);
                *(float2*)&out[(size_t)r1 * CIN + col] = o;
            }
        }
    }
}

// ---------------------------------------------------------------------------
extern "C" void kernel_launch(void* const* d_in, const int* in_sizes, int n_in,
                              void* d_out, int out_size) {
    const float* feats = (const float*)d_in[0];
    const void*  coords = d_in[1];
    const float* w1 = (const float*)d_in[2];
    const float* w2 = (const float*)d_in[3];
    const float* w3 = (const float*)d_in[4];
    const float* s1 = (const float*)d_in[5];
    const float* b1 = (const float*)d_in[6];
    const float* s2 = (const float*)d_in[7];
    const float* b2 = (const float*)d_in[8];
    const float* s3 = (const float*)d_in[9];
    const float* b3 = (const float*)d_in[10];
    float* out = (float*)d_out;

    k_init_map<<<(HH * WW + 255) / 256, 256>>>();
    k_scatter<<<(NPTS + 255) / 256, 256>>>(coords);
    k_prep<<<(17 * 1024 + 255) / 256, 256>>>(w1, w2, w3);
    k_conv1<<<NTILES, 256>>>(feats, s1, b1);
    k_conv2<<<NTILES, 256>>>(s2, b2);
    k_conv3<<<NTILES, 256>>>(feats, s3, b3, out);
}